// round 6
// baseline (speedup 1.0000x reference)
#include <cuda_runtime.h>

#define Bb 1024
#define Nn 16
#define Ii 256
#define Hh 1024
#define H3 3072

typedef unsigned long long u64;

// ---------------- scratch (device globals; no allocation allowed) ----------
__device__ __align__(256) float g_gie [Bb*Nn*H3];   // encoder input-gates (precomputed)
__device__ __align__(256) float g_henc[Bb*Nn*Hh];   // encoder hidden states
__device__ __align__(256) float g_w1xe[Bb*Nn*Hh];   // henc @ W1
__device__ __align__(256) float g_h   [Bb*Hh];      // current hidden
__device__ __align__(256) float g_heff[Bb*Hh];      // mixed hidden (decoder)
__device__ __align__(256) float g_gh  [Bb*H3];      // hidden-gates scratch
__device__ __align__(256) float g_gid [Bb*H3];      // decoder input-gates scratch
__device__ __align__(256) float g_hw2 [Bb*Hh];      // hidden @ W2
__device__ __align__(256) float g_inp [Bb*Ii];      // decoder input step
__device__ __align__(256) float g_u   [Bb*Nn];      // attention logits
__device__ __align__(256) float g_tgate[Nn*Bb];     // t_gate, layout [step][b]
__device__ __align__(256) int   g_idx  [Nn*Bb];     // idx_seq, layout [step][b]

// ---------------- helpers ---------------------------------------------------
__device__ __forceinline__ u64 dup2(float x) {
    u64 r; asm("mov.b64 %0, {%1, %1};" : "=l"(r) : "f"(x)); return r;
}
__device__ __forceinline__ void fma2(u64 &d, u64 a, u64 b) {
    asm("fma.rn.f32x2 %0, %1, %2, %0;" : "+l"(d) : "l"(a), "l"(b));
}
__device__ __forceinline__ float2 unpk(u64 v) {
    float2 f; asm("mov.b64 {%0, %1}, %2;" : "=f"(f.x), "=f"(f.y) : "l"(v)); return f;
}
__device__ __forceinline__ float fsig(float x) {
    return __fdividef(1.0f, 1.0f + __expf(-x));      // robust at +-inf
}
__device__ __forceinline__ float ftanh(float x) {
    // 1 - 2/(e^{2x}+1): exact limits at +-inf, ~1e-7 abs error
    return 1.0f - __fdividef(2.0f, __expf(2.0f * x) + 1.0f);
}

// ---------------- SGEMM -----------------------------------------------------
// C(M,N) = A(M,K) @ op(B) + bias,   BT: B is (N,K) row-major -> C = A@B^T
//                                  !BT: B is (K,N) row-major -> C = A@B
// GATE: A rows scaled by gate[m] before multiply.
// 128x128x16 tile, 256 threads, 8x8 per thread, packed f32x2 FMA.
template<bool BT, bool GATE>
__global__ __launch_bounds__(256, 2)
void sgemm(const float* __restrict__ A, const float* __restrict__ B,
           const float* __restrict__ bias, const float* __restrict__ gate,
           float* __restrict__ C, int M, int N, int K)
{
    __shared__ __align__(16) u64   As2[16][128];   // A values duplicated (lo=hi)
    __shared__ __align__(16) float Bs [16][128];

    const int tid = threadIdx.x;
    const int tx  = tid & 15;    // column group: cols tx*8 .. tx*8+7
    const int ty  = tid >> 4;    // row group:    rows ty*8 .. ty*8+7
    const int bm  = blockIdx.y * 128;
    const int bn  = blockIdx.x * 128;
    const int nkb = K >> 4;

    // load-index precompute
    const int ar0 = tid >> 2;          // A rows: ar0, ar0+64
    const int ac4 = tid & 3;           // A k-group (float4)
    const int bkr = tid >> 5;          // !BT: B k-rows: bkr, bkr+8
    const int bc4 = tid & 31;          // !BT: B col-group

    float4 pa[2], pb[2];
    float  ga[2] = {1.0f, 1.0f};
    if (GATE) { ga[0] = gate[bm + ar0]; ga[1] = gate[bm + ar0 + 64]; }

    auto loadA = [&](int kb) {
        pa[0] = *reinterpret_cast<const float4*>(A + (size_t)(bm + ar0     ) * K + kb*16 + ac4*4);
        pa[1] = *reinterpret_cast<const float4*>(A + (size_t)(bm + ar0 + 64) * K + kb*16 + ac4*4);
    };
    auto loadB = [&](int kb) {
        if (BT) {
            pb[0] = *reinterpret_cast<const float4*>(B + (size_t)(bn + ar0     ) * K + kb*16 + ac4*4);
            pb[1] = *reinterpret_cast<const float4*>(B + (size_t)(bn + ar0 + 64) * K + kb*16 + ac4*4);
        } else {
            pb[0] = *reinterpret_cast<const float4*>(B + (size_t)(kb*16 + bkr    ) * N + bn + bc4*4);
            pb[1] = *reinterpret_cast<const float4*>(B + (size_t)(kb*16 + bkr + 8) * N + bn + bc4*4);
        }
    };
    auto stash = [&]() {
        #pragma unroll
        for (int i = 0; i < 2; i++) {
            int row = ar0 + 64*i;
            float g = GATE ? ga[i] : 1.0f;
            float4 v = pa[i];
            As2[ac4*4+0][row] = dup2(v.x * g);
            As2[ac4*4+1][row] = dup2(v.y * g);
            As2[ac4*4+2][row] = dup2(v.z * g);
            As2[ac4*4+3][row] = dup2(v.w * g);
        }
        if (BT) {
            #pragma unroll
            for (int i = 0; i < 2; i++) {
                int row = ar0 + 64*i;
                float4 v = pb[i];
                Bs[ac4*4+0][row] = v.x;
                Bs[ac4*4+1][row] = v.y;
                Bs[ac4*4+2][row] = v.z;
                Bs[ac4*4+3][row] = v.w;
            }
        } else {
            *reinterpret_cast<float4*>(&Bs[bkr    ][bc4*4]) = pb[0];
            *reinterpret_cast<float4*>(&Bs[bkr + 8][bc4*4]) = pb[1];
        }
    };

    u64 acc[8][4];
    #pragma unroll
    for (int i = 0; i < 8; i++)
        #pragma unroll
        for (int p = 0; p < 4; p++) acc[i][p] = 0ull;

    loadA(0); loadB(0);
    stash();
    __syncthreads();

    for (int kb = 0; kb < nkb; kb++) {
        bool last = (kb == nkb - 1);
        if (!last) { loadA(kb + 1); loadB(kb + 1); }
        #pragma unroll
        for (int kk = 0; kk < 16; kk++) {
            const ulonglong2* arow = reinterpret_cast<const ulonglong2*>(&As2[kk][ty*8]);
            ulonglong2 a0 = arow[0], a1 = arow[1], a2 = arow[2], a3 = arow[3];
            const ulonglong2* brow = reinterpret_cast<const ulonglong2*>(&Bs[kk][tx*8]);
            ulonglong2 b0 = brow[0], b1 = brow[1];
            u64 av[8] = {a0.x, a0.y, a1.x, a1.y, a2.x, a2.y, a3.x, a3.y};
            u64 bv[4] = {b0.x, b0.y, b1.x, b1.y};
            #pragma unroll
            for (int i = 0; i < 8; i++)
                #pragma unroll
                for (int p = 0; p < 4; p++)
                    fma2(acc[i][p], av[i], bv[p]);
        }
        __syncthreads();
        if (!last) { stash(); __syncthreads(); }
    }

    #pragma unroll
    for (int i = 0; i < 8; i++) {
        float* crow = C + (size_t)(bm + ty*8 + i) * N + bn + tx*8;
        #pragma unroll
        for (int p = 0; p < 4; p++) {
            float2 vv = unpk(acc[i][p]);
            if (bias) {
                vv.x += bias[bn + tx*8 + 2*p];
                vv.y += bias[bn + tx*8 + 2*p + 1];
            }
            reinterpret_cast<float2*>(crow)[p] = vv;
        }
    }
}

// ---------------- small kernels ---------------------------------------------
__global__ void setup_kernel(const float* __restrict__ phis) {
    int id = blockIdx.x * 256 + threadIdx.x;       // B*N threads
    if (id >= Bb * Nn) return;
    int b = id >> 4, n = id & 15;
    const float* prow = phis + (size_t)(b * Nn + n) * Nn;
    float s = 0.0f;
    #pragma unroll
    for (int k = 0; k < Nn; k++) s += prow[k];
    int ns = (int)(s + 0.5f);                       // phis entries are exact 0/1
    g_tgate[n * Bb + b] = (n == 0) ? 1.0f : prow[n - 1];   // phis[b, n, n-1]
    g_idx[n * Bb + b] = (ns + n - 1) & (Nn - 1);
}

__global__ void zero_h_kernel() {
    g_h[blockIdx.x * 256 + threadIdx.x] = 0.0f;
}

__global__ void enc_combine(int t) {
    int id = blockIdx.x * 256 + threadIdx.x;       // B*H
    int b = id >> 10, h = id & 1023;
    float tg = g_tgate[t * Bb + b];
    float hg = tg * g_h[id];                        // gated previous hidden
    const float* gi = g_gie + (size_t)(b * Nn + t) * H3;
    const float* gh = g_gh  + (size_t)b * H3;       // already from gated h (GATE gemm)
    float r = fsig(gi[h] + gh[h]);
    float z = fsig(gi[Hh + h] + gh[Hh + h]);
    float g = ftanh(gi[2*Hh + h] + r * gh[2*Hh + h]);
    float hn = (1.0f - z) * g + z * hg;
    g_h[id] = hn;
    g_henc[(size_t)(b * Nn + t) * Hh + h] = hn;
}

__global__ void dec_init(const float* __restrict__ init_token) {
    int id = blockIdx.x * 256 + threadIdx.x;       // B*H
    int b = id >> 10, h = id & 1023;
    int idx = g_idx[b];                             // step-0 index = (Ns[b,0]-1)%N
    g_h[id] = g_henc[(size_t)(b * Nn + idx) * Hh + h];
    if (h < Ii) g_inp[b * Ii + h] = init_token[h];
}

__global__ void mix_kernel(const float* __restrict__ init_token, int t) {
    int id = blockIdx.x * 256 + threadIdx.x;       // B*H
    int b = id >> 10, h = id & 1023;
    float tg = g_tgate[t * Bb + b];
    int idx = g_idx[t * Bb + b];
    float ih = g_henc[(size_t)(b * Nn + idx) * Hh + h];
    g_heff[id] = tg * g_h[id] + (1.0f - tg) * ih;
    if (h < Ii) {
        int j = b * Ii + h;
        g_inp[j] = tg * g_inp[j] + (1.0f - tg) * init_token[h];
    }
}

__global__ void dec_combine() {
    int id = blockIdx.x * 256 + threadIdx.x;       // B*H
    int b = id >> 10, h = id & 1023;
    float hg = g_heff[id];
    const float* gi = g_gid + (size_t)b * H3;
    const float* gh = g_gh  + (size_t)b * H3;
    float r = fsig(gi[h] + gh[h]);
    float z = fsig(gi[Hh + h] + gh[Hh + h]);
    float g = ftanh(gi[2*Hh + h] + r * gh[2*Hh + h]);
    g_h[id] = (1.0f - z) * g + z * hg;
}

__global__ void u_kernel(const float* __restrict__ v) {
    int bn = blockIdx.x;                            // b*16 + n
    int b = bn >> 4;
    int i = threadIdx.x;                            // 256 threads x 4 h each
    float4 w  = reinterpret_cast<const float4*>(g_w1xe + (size_t)bn * Hh)[i];
    float4 hw = reinterpret_cast<const float4*>(g_hw2  + (size_t)b  * Hh)[i];
    float4 vv = reinterpret_cast<const float4*>(v)[i];
    float s = ftanh(w.x + hw.x) * vv.x + ftanh(w.y + hw.y) * vv.y
            + ftanh(w.z + hw.z) * vv.z + ftanh(w.w + hw.w) * vv.w;
    #pragma unroll
    for (int o = 16; o; o >>= 1) s += __shfl_xor_sync(0xffffffffu, s, o);
    __shared__ float red[8];
    if ((i & 31) == 0) red[i >> 5] = s;
    __syncthreads();
    if (i < 8) {
        float r2 = red[i];
        #pragma unroll
        for (int o = 4; o; o >>= 1) r2 += __shfl_xor_sync(0xffu, r2, o);
        if (i == 0) g_u[bn] = r2;
    }
}

__global__ void attn_kernel(const float* __restrict__ phis, const float* __restrict__ input,
                            float* __restrict__ out, int t) {
    __shared__ float sat[Nn];
    int b = blockIdx.x, tid = threadIdx.x;
    if (tid < Nn) {
        float mask = phis[(size_t)(b * Nn + t) * Nn + tid];
        float um = g_u[b * Nn + tid] * mask;
        float m = um;
        #pragma unroll
        for (int o = 8; o; o >>= 1) m = fmaxf(m, __shfl_xor_sync(0xffffu, m, o));
        float e = __expf(um - m) * mask;
        float ssum = e;
        #pragma unroll
        for (int o = 8; o; o >>= 1) ssum += __shfl_xor_sync(0xffffu, ssum, o);
        float a = e / ssum;
        sat[tid] = a;
        out[(size_t)(b * Nn + t) * Nn + tid] = a;   // out[b, t, n]
    }
    __syncthreads();
    // inp_step[b, i] = sum_n attn[b,n] * input[b,n,i]
    float s = 0.0f;
    const float* irow = input + (size_t)b * Nn * Ii + tid;
    #pragma unroll
    for (int n = 0; n < Nn; n++) s += sat[n] * irow[n * Ii];
    g_inp[b * Ii + tid] = s;
}

// ---------------- driver ------------------------------------------------------
extern "C" void kernel_launch(void* const* d_in, const int* in_sizes, int n_in,
                              void* d_out, int out_size) {
    const float* input      = (const float*)d_in[0];
    const float* phis       = (const float*)d_in[1];
    const float* init_token = (const float*)d_in[2];
    const float* W1         = (const float*)d_in[3];
    const float* W2         = (const float*)d_in[4];
    const float* v          = (const float*)d_in[5];
    const float* Wih_e      = (const float*)d_in[6];
    const float* Whh_e      = (const float*)d_in[7];
    const float* bih_e      = (const float*)d_in[8];
    const float* bhh_e      = (const float*)d_in[9];
    const float* Wih_d      = (const float*)d_in[10];
    const float* Whh_d      = (const float*)d_in[11];
    const float* bih_d      = (const float*)d_in[12];
    const float* bhh_d      = (const float*)d_in[13];
    float* out = (float*)d_out;

    float *p_gie, *p_henc, *p_w1xe, *p_h, *p_heff, *p_gh, *p_gid, *p_hw2, *p_inp, *p_tg;
    cudaGetSymbolAddress((void**)&p_gie,  g_gie);
    cudaGetSymbolAddress((void**)&p_henc, g_henc);
    cudaGetSymbolAddress((void**)&p_w1xe, g_w1xe);
    cudaGetSymbolAddress((void**)&p_h,    g_h);
    cudaGetSymbolAddress((void**)&p_heff, g_heff);
    cudaGetSymbolAddress((void**)&p_gh,   g_gh);
    cudaGetSymbolAddress((void**)&p_gid,  g_gid);
    cudaGetSymbolAddress((void**)&p_hw2,  g_hw2);
    cudaGetSymbolAddress((void**)&p_inp,  g_inp);
    cudaGetSymbolAddress((void**)&p_tg,   g_tgate);

    const int EW_BLOCKS = (Bb * Hh) / 256;          // 4096

    setup_kernel<<<(Bb * Nn + 255) / 256, 256>>>(phis);
    zero_h_kernel<<<EW_BLOCKS, 256>>>();

    // gi_e = input @ Wih_e^T + bih_e   (16384 x 3072, K=256)
    sgemm<true, false><<<dim3(H3/128, (Bb*Nn)/128), 256>>>(
        input, Wih_e, bih_e, nullptr, p_gie, Bb*Nn, H3, Ii);

    // encoder
    for (int t = 0; t < Nn; t++) {
        // gh = (tg * h) @ Whh_e^T + bhh_e   (1024 x 3072, K=1024), row gate
        sgemm<true, true><<<dim3(H3/128, Bb/128), 256>>>(
            p_h, Whh_e, bhh_e, p_tg + t*Bb, p_gh, Bb, H3, Hh);
        enc_combine<<<EW_BLOCKS, 256>>>(t);
    }

    // W1xe = henc @ W1   (16384 x 1024, K=1024)
    sgemm<false, false><<<dim3(Hh/128, (Bb*Nn)/128), 256>>>(
        p_henc, W1, nullptr, nullptr, p_w1xe, Bb*Nn, Hh, Hh);

    dec_init<<<EW_BLOCKS, 256>>>(init_token);

    // decoder
    for (int t = 0; t < Nn; t++) {
        mix_kernel<<<EW_BLOCKS, 256>>>(init_token, t);
        // gi_d = inp @ Wih_d^T + bih_d   (1024 x 3072, K=256)
        sgemm<true, false><<<dim3(H3/128, Bb/128), 256>>>(
            p_inp, Wih_d, bih_d, nullptr, p_gid, Bb, H3, Ii);
        // gh_d = heff @ Whh_d^T + bhh_d  (1024 x 3072, K=1024)
        sgemm<true, false><<<dim3(H3/128, Bb/128), 256>>>(
            p_heff, Whh_d, bhh_d, nullptr, p_gh, Bb, H3, Hh);
        dec_combine<<<EW_BLOCKS, 256>>>();
        // hW2 = h @ W2   (1024 x 1024, K=1024)
        sgemm<false, false><<<dim3(Hh/128, Bb/128), 256>>>(
            p_h, W2, nullptr, nullptr, p_hw2, Bb, Hh, Hh);
        u_kernel<<<Bb * Nn, 256>>>(v);
        attn_kernel<<<Bb, 256>>>(phis, input, out, t);
    }
}